// round 4
// baseline (speedup 1.0000x reference)
#include <cuda_runtime.h>
#include <mma.h>
#include <math.h>
#include <stdint.h>

using namespace nvcuda;

#define Bn 4
#define Tn 2048
#define Dn 1024
#define Hn 16
#define HDn 64
#define MROWS (Bn*Tn)      // 8192
#define QKVN (3*Dn)        // 3072

__device__ float g_qkv[(size_t)MROWS * QKVN];
__device__ float g_attn[(size_t)MROWS * Dn];

__device__ __forceinline__ float to_tf32(float x) {
    uint32_t u;
    asm("cvt.rna.tf32.f32 %0, %1;" : "=r"(u) : "f"(x));
    return __uint_as_float(u);
}
__device__ __forceinline__ uint32_t s2u(const void* p) {
    return (uint32_t)__cvta_generic_to_shared(p);
}
__device__ __forceinline__ void cp16(uint32_t dst, const void* src) {
    asm volatile("cp.async.cg.shared.global [%0], [%1], 16;" :: "r"(dst), "l"(src));
}
__device__ __forceinline__ void cp_commit() { asm volatile("cp.async.commit_group;"); }
__device__ __forceinline__ void cp_wait0()  { asm volatile("cp.async.wait_group 0;"); }

template <class Frag>
__device__ __forceinline__ void frag_tf32(Frag& f) {
    #pragma unroll
    for (int t = 0; t < f.num_elements; t++) f.x[t] = to_tf32(f.x[t]);
}

// ---------------------------------------------------------------------------
// TF32 GEMM v2: 128x128 tile, BK=32, cp.async double buffer, cvt in frags.
// ---------------------------------------------------------------------------
#define AP_A 36                       // A row pitch (floats)
#define AP_B 136                      // B row pitch
#define A_STG (128*AP_A)              // floats per stage
#define B_STG (32*AP_B)
#define GEMM_SMEM ((2*A_STG + 2*B_STG) * 4)

__global__ void __launch_bounds__(256) gemm_tf32_v2(
    const float* __restrict__ A, const float* __restrict__ Bm,
    float* __restrict__ C, int M, int N, int K)
{
    extern __shared__ float sm[];
    float* As = sm;                   // [2][128][AP_A]
    float* Bs = sm + 2*A_STG;         // [2][32][AP_B]

    const int tid = threadIdx.x;
    const int bm = blockIdx.y * 128;
    const int bn = blockIdx.x * 128;
    const int w  = tid >> 5;
    const int wm = (w >> 2) * 64;
    const int wn = (w & 3) * 32;

    wmma::fragment<wmma::accumulator, 16, 16, 8, float> acc[4][2];
    #pragma unroll
    for (int i = 0; i < 4; i++)
        #pragma unroll
        for (int j = 0; j < 2; j++) wmma::fill_fragment(acc[i][j], 0.f);

    const int nk = K / 32;

    // prefetch helper indices: A 1024 chunks, B 1024 chunks, 4+4 per thread
    auto prefetch = [&](int kt, int stg) {
        const int k0 = kt * 32;
        float* ad = As + stg * A_STG;
        float* bd = Bs + stg * B_STG;
        #pragma unroll
        for (int i = 0; i < 4; i++) {
            int id = tid + 256*i;
            int r = id >> 3, c = (id & 7) * 4;
            cp16(s2u(ad + r*AP_A + c), &A[(size_t)(bm + r) * K + k0 + c]);
        }
        #pragma unroll
        for (int i = 0; i < 4; i++) {
            int id = tid + 256*i;
            int r = id >> 5, c = (id & 31) * 4;
            cp16(s2u(bd + r*AP_B + c), &Bm[(size_t)(k0 + r) * N + bn + c]);
        }
        cp_commit();
    };

    prefetch(0, 0);
    int stg = 0;

    for (int kt = 0; kt < nk; kt++) {
        cp_wait0();
        __syncthreads();
        if (kt + 1 < nk) prefetch(kt + 1, stg ^ 1);

        const float* a0 = As + stg * A_STG;
        const float* b0 = Bs + stg * B_STG;
        #pragma unroll
        for (int kk = 0; kk < 4; kk++) {
            wmma::fragment<wmma::matrix_a, 16, 16, 8, wmma::precision::tf32, wmma::row_major> af[4];
            wmma::fragment<wmma::matrix_b, 16, 16, 8, wmma::precision::tf32, wmma::row_major> bf[2];
            #pragma unroll
            for (int i = 0; i < 4; i++) {
                wmma::load_matrix_sync(af[i], a0 + (wm + i*16)*AP_A + kk*8, AP_A);
                frag_tf32(af[i]);
            }
            #pragma unroll
            for (int j = 0; j < 2; j++) {
                wmma::load_matrix_sync(bf[j], b0 + (kk*8)*AP_B + wn + j*16, AP_B);
                frag_tf32(bf[j]);
            }
            #pragma unroll
            for (int i = 0; i < 4; i++)
                #pragma unroll
                for (int j = 0; j < 2; j++)
                    wmma::mma_sync(acc[i][j], af[i], bf[j], acc[i][j]);
        }
        stg ^= 1;
        __syncthreads();
    }

    #pragma unroll
    for (int i = 0; i < 4; i++)
        #pragma unroll
        for (int j = 0; j < 2; j++)
            wmma::store_matrix_sync(&C[(size_t)(bm + wm + i*16) * N + bn + wn + j*16],
                                    acc[i][j], N, wmma::mem_row_major);
}

// Bias add
__global__ void __launch_bounds__(256) bias_add_kernel(
    float* __restrict__ out, const float* __restrict__ bias, int total4, int N)
{
    int idx = blockIdx.x * blockDim.x + threadIdx.x;
    if (idx >= total4) return;
    int col = (idx * 4) & (N - 1);
    float4 v = *(float4*)&out[idx * 4];
    v.x += bias[col+0]; v.y += bias[col+1];
    v.z += bias[col+2]; v.w += bias[col+3];
    *(float4*)&out[idx * 4] = v;
}

// ---------------------------------------------------------------------------
// RoPE + L2 normalize q,k in place. One warp per (b,t,h,q|k).
// ---------------------------------------------------------------------------
__global__ void __launch_bounds__(256) rope_norm_kernel(float* __restrict__ qkv)
{
    const int gw = (blockIdx.x * blockDim.x + threadIdx.x) >> 5;
    const int lane = threadIdx.x & 31;
    const int which = gw & 1;
    const int h = (gw >> 1) & (Hn - 1);
    const int t = (gw >> 5) & (Tn - 1);
    const int b = gw >> 16;

    float* p = qkv + (size_t)(b*Tn + t) * QKVN + which*Dn + h*HDn;

    const float inv_freq = powf(10000.f, -(float)lane * (1.f/32.f));
    const float ang = (float)t * inv_freq;
    float s, c;
    sincosf(ang, &s, &c);

    const float x1 = p[lane];
    const float x2 = p[lane + 32];
    const float r1 = x1*c - x2*s;
    const float r2 = x1*s + x2*c;

    float ss = r1*r1 + r2*r2;
    #pragma unroll
    for (int off = 16; off; off >>= 1)
        ss += __shfl_xor_sync(0xffffffffu, ss, off);

    const float inv = rsqrtf(ss + 1e-6f);
    p[lane]      = r1 * inv;
    p[lane + 32] = r2 * inv;
}

// ---------------------------------------------------------------------------
// TF32 flash attention v2: cp.async double-buffered K/V, cvt in fragments.
// Block = 128 q rows of one (b,h); warp w owns rows 16w..16w+15.
// q,k unit vectors -> |score|<=0.125 -> exp without max/rescale.
// ---------------------------------------------------------------------------
#define AP 72
#define KV_STG (64*AP)
#define ATT_SMEM ((128*AP + 2*KV_STG + 2*KV_STG + 128*AP + 128) * 4)

__global__ void __launch_bounds__(256) attn_tc_kernel(
    const float* __restrict__ qkv, float* __restrict__ outp)
{
    extern __shared__ float sm[];
    float* Qs   = sm;                        // 128 x AP (tf32)
    float* Ks   = Qs + 128*AP;               // 2 x 64 x AP (raw f32)
    float* Vs   = Ks + 2*KV_STG;             // 2 x 64 x AP
    float* Ps   = Vs + 2*KV_STG;             // 128 x AP
    float* lrow = Ps + 128*AP;               // 128

    const int tid  = threadIdx.x;
    const int w    = tid >> 5;
    const int lane = tid & 31;

    const int qt = blockIdx.x & 15;
    const int h  = (blockIdx.x >> 4) & (Hn-1);
    const int b  = blockIdx.x >> 8;
    const int q0 = qt * 128;

    const float* qbase = qkv + (size_t)(b*Tn) * QKVN + h*HDn;
    const float* kbase = qbase + Dn;
    const float* vbase = qbase + 2*Dn;

    auto prefetch_kv = [&](int kt, int stg) {
        float* kd = Ks + stg*KV_STG;
        float* vd = Vs + stg*KV_STG;
        #pragma unroll
        for (int i = 0; i < 4; i++) {
            int id = tid + 256*i;
            int r = id >> 4, c = (id & 15) * 4;
            cp16(s2u(kd + r*AP + c), kbase + (size_t)(kt*64 + r) * QKVN + c);
        }
        #pragma unroll
        for (int i = 0; i < 4; i++) {
            int id = tid + 256*i;
            int r = id >> 4, c = (id & 15) * 4;
            cp16(s2u(vd + r*AP + c), vbase + (size_t)(kt*64 + r) * QKVN + c);
        }
        cp_commit();
    };

    prefetch_kv(0, 0);

    // Load Q tile, scale, cvt tf32
    {
        const int r  = tid >> 1;
        const int c0 = (tid & 1) * 32;
        const float* src = qbase + (size_t)(q0 + r) * QKVN + c0;
        float* dst = Qs + r*AP + c0;
        #pragma unroll
        for (int j = 0; j < 8; j++) {
            float4 v = *(const float4*)(src + j*4);
            dst[j*4+0] = to_tf32(0.125f * v.x);
            dst[j*4+1] = to_tf32(0.125f * v.y);
            dst[j*4+2] = to_tf32(0.125f * v.z);
            dst[j*4+3] = to_tf32(0.125f * v.w);
        }
    }
    if (tid < 128) lrow[tid] = 0.f;

    wmma::fragment<wmma::accumulator, 16, 16, 8, float> oacc[4];
    #pragma unroll
    for (int j = 0; j < 4; j++) wmma::fill_fragment(oacc[j], 0.f);

    const int rowm = w * 16;
    int stg = 0;

    for (int kt = 0; kt < Tn/64; kt++) {
        cp_wait0();
        __syncthreads();
        if (kt + 1 < Tn/64) prefetch_kv(kt + 1, stg ^ 1);

        const float* kc = Ks + stg*KV_STG;
        const float* vc = Vs + stg*KV_STG;

        // S = Q @ K^T
        wmma::fragment<wmma::accumulator, 16, 16, 8, float> sacc[4];
        #pragma unroll
        for (int j = 0; j < 4; j++) wmma::fill_fragment(sacc[j], 0.f);
        #pragma unroll
        for (int ks = 0; ks < 8; ks++) {
            wmma::fragment<wmma::matrix_a, 16, 16, 8, wmma::precision::tf32, wmma::row_major> aq;
            wmma::load_matrix_sync(aq, Qs + rowm*AP + ks*8, AP);
            #pragma unroll
            for (int j = 0; j < 4; j++) {
                wmma::fragment<wmma::matrix_b, 16, 16, 8, wmma::precision::tf32, wmma::col_major> bk;
                wmma::load_matrix_sync(bk, kc + j*16*AP + ks*8, AP);
                frag_tf32(bk);
                wmma::mma_sync(sacc[j], aq, bk, sacc[j]);
            }
        }
        #pragma unroll
        for (int j = 0; j < 4; j++)
            wmma::store_matrix_sync(Ps + rowm*AP + j*16, sacc[j], AP, wmma::mem_row_major);
        __syncwarp();

        // P = exp(S); accumulate row sums. No max needed.
        {
            const int rr = rowm + (lane >> 1);
            const int cc = (lane & 1) * 32;
            float* pr = Ps + rr*AP + cc;
            float sum = 0.f;
            #pragma unroll
            for (int j = 0; j < 32; j++) {
                float e = __expf(pr[j]);
                sum += e;
                pr[j] = to_tf32(e);
            }
            sum += __shfl_xor_sync(0xffffffffu, sum, 1);
            if (!(lane & 1)) lrow[rr] += sum;
        }
        __syncwarp();

        // O += P @ V
        #pragma unroll
        for (int ks = 0; ks < 8; ks++) {
            wmma::fragment<wmma::matrix_a, 16, 16, 8, wmma::precision::tf32, wmma::row_major> ap;
            wmma::load_matrix_sync(ap, Ps + rowm*AP + ks*8, AP);
            #pragma unroll
            for (int j = 0; j < 4; j++) {
                wmma::fragment<wmma::matrix_b, 16, 16, 8, wmma::precision::tf32, wmma::row_major> bv;
                wmma::load_matrix_sync(bv, vc + ks*8*AP + j*16, AP);
                frag_tf32(bv);
                wmma::mma_sync(oacc[j], ap, bv, oacc[j]);
            }
        }
        stg ^= 1;
        __syncthreads();
    }

    #pragma unroll
    for (int j = 0; j < 4; j++)
        wmma::store_matrix_sync(Ps + rowm*AP + j*16, oacc[j], AP, wmma::mem_row_major);
    __syncthreads();

    {
        const int r  = tid >> 1;
        const int c0 = (tid & 1) * 32;
        const float inv = 1.f / lrow[r];
        const float* srcr = Ps + r*AP + c0;
        float* dst = outp + (size_t)(b*Tn + q0 + r) * Dn + h*HDn + c0;
        #pragma unroll
        for (int j = 0; j < 8; j++) {
            float4 v;
            v.x = srcr[j*4+0] * inv; v.y = srcr[j*4+1] * inv;
            v.z = srcr[j*4+2] * inv; v.w = srcr[j*4+3] * inv;
            *(float4*)(dst + j*4) = v;
        }
    }
}

// ---------------------------------------------------------------------------
extern "C" void kernel_launch(void* const* d_in, const int* in_sizes, int n_in,
                              void* d_out, int out_size)
{
    const float* x    = (const float*)d_in[0];
    const float* Wqkv = (const float*)d_in[1];
    const float* Wo   = (const float*)d_in[2];
    const float* bo   = (const float*)d_in[3];
    float* out = (float*)d_out;

    float* qkv = nullptr;
    float* att = nullptr;
    cudaGetSymbolAddress((void**)&qkv, g_qkv);
    cudaGetSymbolAddress((void**)&att, g_attn);

    cudaFuncSetAttribute(gemm_tf32_v2,
                         cudaFuncAttributeMaxDynamicSharedMemorySize, GEMM_SMEM);
    cudaFuncSetAttribute(attn_tc_kernel,
                         cudaFuncAttributeMaxDynamicSharedMemorySize, ATT_SMEM);

    // 1) qkv = x @ Wqkv
    {
        dim3 grid(QKVN/128, MROWS/128);
        gemm_tf32_v2<<<grid, 256, GEMM_SMEM>>>(x, Wqkv, qkv, MROWS, QKVN, Dn);
    }
    // 2) RoPE + L2 norm
    {
        int warps = Bn*Tn*Hn*2;
        rope_norm_kernel<<<warps/8, 256>>>(qkv);
    }
    // 3) attention
    {
        dim3 grid(Bn * Hn * (Tn/128));
        attn_tc_kernel<<<grid, 256, ATT_SMEM>>>(qkv, att);
    }
    // 4) out = att @ Wo + bo
    {
        dim3 grid(Dn/128, MROWS/128);
        gemm_tf32_v2<<<grid, 256, GEMM_SMEM>>>(att, Wo, out, MROWS, Dn, Dn);
        int total4 = MROWS * Dn / 4;
        bias_add_kernel<<<(total4 + 255)/256, 256>>>(out, bo, total4, Dn);
    }
}

// round 5
// speedup vs baseline: 1.0171x; 1.0171x over previous
#include <cuda_runtime.h>
#include <mma.h>
#include <math.h>
#include <stdint.h>

using namespace nvcuda;

#define Bn 4
#define Tn 2048
#define Dn 1024
#define Hn 16
#define HDn 64
#define MROWS (Bn*Tn)      // 8192
#define QKVN (3*Dn)        // 3072

__device__ float g_qkv[(size_t)MROWS * QKVN];   // qkv activations
__device__ float g_attn[(size_t)MROWS * Dn];    // attention output
__device__ float g_xr[(size_t)MROWS * Dn];      // tf32-rounded x
__device__ float g_wq[(size_t)Dn * QKVN];       // tf32-rounded Wqkv
__device__ float g_wo[(size_t)Dn * Dn];         // tf32-rounded Wo

__device__ __forceinline__ float to_tf32(float x) {
    uint32_t u;
    asm("cvt.rna.tf32.f32 %0, %1;" : "=r"(u) : "f"(x));
    return __uint_as_float(u);
}
__device__ __forceinline__ uint32_t s2u(const void* p) {
    return (uint32_t)__cvta_generic_to_shared(p);
}
__device__ __forceinline__ void cp16(uint32_t dst, const void* src) {
    asm volatile("cp.async.cg.shared.global [%0], [%1], 16;" :: "r"(dst), "l"(src));
}
__device__ __forceinline__ void cp_commit() { asm volatile("cp.async.commit_group;"); }
__device__ __forceinline__ void cp_wait0()  { asm volatile("cp.async.wait_group 0;"); }

// Elementwise tf32 pre-round: dst[i] = round_tf32(src[i])
__global__ void __launch_bounds__(256) preround_kernel(
    const float* __restrict__ src, float* __restrict__ dst, int total4)
{
    int idx = blockIdx.x * blockDim.x + threadIdx.x;
    if (idx >= total4) return;
    float4 v = *(const float4*)&src[idx * 4];
    v.x = to_tf32(v.x); v.y = to_tf32(v.y);
    v.z = to_tf32(v.z); v.w = to_tf32(v.w);
    *(float4*)&dst[idx * 4] = v;
}

// ---------------------------------------------------------------------------
// TF32 GEMM: 128x128 tile, BK=32, cp.async double buffer. Inputs MUST be
// pre-rounded to tf32; no cvt in the hot loop. ROUND_OUT rounds C to tf32.
// ---------------------------------------------------------------------------
#define AP_A 36
#define AP_B 132
#define A_STG (128*AP_A)
#define B_STG (32*AP_B)
#define GEMM_SMEM ((2*A_STG + 2*B_STG) * 4)

template <int ROUND_OUT>
__global__ void __launch_bounds__(256) gemm_tf32_v3(
    const float* __restrict__ A, const float* __restrict__ Bm,
    float* __restrict__ C, int M, int N, int K)
{
    extern __shared__ float sm[];
    float* As = sm;
    float* Bs = sm + 2*A_STG;

    const int tid = threadIdx.x;
    const int bm = blockIdx.y * 128;
    const int bn = blockIdx.x * 128;
    const int w  = tid >> 5;
    const int wm = (w >> 2) * 64;
    const int wn = (w & 3) * 32;

    wmma::fragment<wmma::accumulator, 16, 16, 8, float> acc[4][2];
    #pragma unroll
    for (int i = 0; i < 4; i++)
        #pragma unroll
        for (int j = 0; j < 2; j++) wmma::fill_fragment(acc[i][j], 0.f);

    const int nk = K / 32;

    auto prefetch = [&](int kt, int stg) {
        const int k0 = kt * 32;
        float* ad = As + stg * A_STG;
        float* bd = Bs + stg * B_STG;
        #pragma unroll
        for (int i = 0; i < 4; i++) {
            int id = tid + 256*i;
            int r = id >> 3, c = (id & 7) * 4;
            cp16(s2u(ad + r*AP_A + c), &A[(size_t)(bm + r) * K + k0 + c]);
        }
        #pragma unroll
        for (int i = 0; i < 4; i++) {
            int id = tid + 256*i;
            int r = id >> 5, c = (id & 31) * 4;
            cp16(s2u(bd + r*AP_B + c), &Bm[(size_t)(k0 + r) * N + bn + c]);
        }
        cp_commit();
    };

    prefetch(0, 0);
    int stg = 0;

    for (int kt = 0; kt < nk; kt++) {
        cp_wait0();
        __syncthreads();
        if (kt + 1 < nk) prefetch(kt + 1, stg ^ 1);

        const float* a0 = As + stg * A_STG;
        const float* b0 = Bs + stg * B_STG;
        #pragma unroll
        for (int kk = 0; kk < 4; kk++) {
            wmma::fragment<wmma::matrix_a, 16, 16, 8, wmma::precision::tf32, wmma::row_major> af[4];
            wmma::fragment<wmma::matrix_b, 16, 16, 8, wmma::precision::tf32, wmma::row_major> bf[2];
            #pragma unroll
            for (int i = 0; i < 4; i++)
                wmma::load_matrix_sync(af[i], a0 + (wm + i*16)*AP_A + kk*8, AP_A);
            #pragma unroll
            for (int j = 0; j < 2; j++)
                wmma::load_matrix_sync(bf[j], b0 + (kk*8)*AP_B + wn + j*16, AP_B);
            #pragma unroll
            for (int i = 0; i < 4; i++)
                #pragma unroll
                for (int j = 0; j < 2; j++)
                    wmma::mma_sync(acc[i][j], af[i], bf[j], acc[i][j]);
        }
        stg ^= 1;
        __syncthreads();
    }

    #pragma unroll
    for (int i = 0; i < 4; i++)
        #pragma unroll
        for (int j = 0; j < 2; j++) {
            if (ROUND_OUT) {
                #pragma unroll
                for (int t = 0; t < acc[i][j].num_elements; t++)
                    acc[i][j].x[t] = to_tf32(acc[i][j].x[t]);
            }
            wmma::store_matrix_sync(&C[(size_t)(bm + wm + i*16) * N + bn + wn + j*16],
                                    acc[i][j], N, wmma::mem_row_major);
        }
}

// Bias add
__global__ void __launch_bounds__(256) bias_add_kernel(
    float* __restrict__ out, const float* __restrict__ bias, int total4, int N)
{
    int idx = blockIdx.x * blockDim.x + threadIdx.x;
    if (idx >= total4) return;
    int col = (idx * 4) & (N - 1);
    float4 v = *(float4*)&out[idx * 4];
    v.x += bias[col+0]; v.y += bias[col+1];
    v.z += bias[col+2]; v.w += bias[col+3];
    *(float4*)&out[idx * 4] = v;
}

// ---------------------------------------------------------------------------
// RoPE + L2 norm, writes tf32-rounded q,k in place.
// ---------------------------------------------------------------------------
__global__ void __launch_bounds__(256) rope_norm_kernel(float* __restrict__ qkv)
{
    const int gw = (blockIdx.x * blockDim.x + threadIdx.x) >> 5;
    const int lane = threadIdx.x & 31;
    const int which = gw & 1;
    const int h = (gw >> 1) & (Hn - 1);
    const int t = (gw >> 5) & (Tn - 1);
    const int b = gw >> 16;

    float* p = qkv + (size_t)(b*Tn + t) * QKVN + which*Dn + h*HDn;

    const float inv_freq = powf(10000.f, -(float)lane * (1.f/32.f));
    const float ang = (float)t * inv_freq;
    float s, c;
    sincosf(ang, &s, &c);

    const float x1 = p[lane];
    const float x2 = p[lane + 32];
    const float r1 = x1*c - x2*s;
    const float r2 = x1*s + x2*c;

    float ss = r1*r1 + r2*r2;
    #pragma unroll
    for (int off = 16; off; off >>= 1)
        ss += __shfl_xor_sync(0xffffffffu, ss, off);

    const float inv = rsqrtf(ss + 1e-6f);
    p[lane]      = to_tf32(r1 * inv);
    p[lane + 32] = to_tf32(r2 * inv);
}

// ---------------------------------------------------------------------------
// TF32 flash attention: cp.async double-buffered K/V, all operands already
// tf32 (q,k from rope; v from GEMM1 epilogue; P rounded after exp).
// Writes tf32-rounded output (feeds out-proj).
// ---------------------------------------------------------------------------
#define AP 72
#define KV_STG (64*AP)
#define ATT_SMEM ((128*AP + 2*KV_STG + 2*KV_STG + 128*AP + 128) * 4)

__global__ void __launch_bounds__(256) attn_tc_kernel(
    const float* __restrict__ qkv, float* __restrict__ outp)
{
    extern __shared__ float sm[];
    float* Qs   = sm;
    float* Ks   = Qs + 128*AP;
    float* Vs   = Ks + 2*KV_STG;
    float* Ps   = Vs + 2*KV_STG;
    float* lrow = Ps + 128*AP;

    const int tid  = threadIdx.x;
    const int w    = tid >> 5;
    const int lane = tid & 31;

    const int qt = blockIdx.x & 15;
    const int h  = (blockIdx.x >> 4) & (Hn-1);
    const int b  = blockIdx.x >> 8;
    const int q0 = qt * 128;

    const float* qbase = qkv + (size_t)(b*Tn) * QKVN + h*HDn;
    const float* kbase = qbase + Dn;
    const float* vbase = qbase + 2*Dn;

    auto prefetch_kv = [&](int kt, int stg) {
        float* kd = Ks + stg*KV_STG;
        float* vd = Vs + stg*KV_STG;
        #pragma unroll
        for (int i = 0; i < 4; i++) {
            int id = tid + 256*i;
            int r = id >> 4, c = (id & 15) * 4;
            cp16(s2u(kd + r*AP + c), kbase + (size_t)(kt*64 + r) * QKVN + c);
        }
        #pragma unroll
        for (int i = 0; i < 4; i++) {
            int id = tid + 256*i;
            int r = id >> 4, c = (id & 15) * 4;
            cp16(s2u(vd + r*AP + c), vbase + (size_t)(kt*64 + r) * QKVN + c);
        }
        cp_commit();
    };

    prefetch_kv(0, 0);

    // Q tile: scale by 1/8 (power of two => stays tf32)
    {
        const int r  = tid >> 1;
        const int c0 = (tid & 1) * 32;
        const float* src = qbase + (size_t)(q0 + r) * QKVN + c0;
        float* dst = Qs + r*AP + c0;
        #pragma unroll
        for (int j = 0; j < 8; j++) {
            float4 v = *(const float4*)(src + j*4);
            dst[j*4+0] = 0.125f * v.x;
            dst[j*4+1] = 0.125f * v.y;
            dst[j*4+2] = 0.125f * v.z;
            dst[j*4+3] = 0.125f * v.w;
        }
    }
    if (tid < 128) lrow[tid] = 0.f;

    wmma::fragment<wmma::accumulator, 16, 16, 8, float> oacc[4];
    #pragma unroll
    for (int j = 0; j < 4; j++) wmma::fill_fragment(oacc[j], 0.f);

    const int rowm = w * 16;
    int stg = 0;

    for (int kt = 0; kt < Tn/64; kt++) {
        cp_wait0();
        __syncthreads();
        if (kt + 1 < Tn/64) prefetch_kv(kt + 1, stg ^ 1);

        const float* kc = Ks + stg*KV_STG;
        const float* vc = Vs + stg*KV_STG;

        // S = Q @ K^T
        wmma::fragment<wmma::accumulator, 16, 16, 8, float> sacc[4];
        #pragma unroll
        for (int j = 0; j < 4; j++) wmma::fill_fragment(sacc[j], 0.f);
        #pragma unroll
        for (int ks = 0; ks < 8; ks++) {
            wmma::fragment<wmma::matrix_a, 16, 16, 8, wmma::precision::tf32, wmma::row_major> aq;
            wmma::load_matrix_sync(aq, Qs + rowm*AP + ks*8, AP);
            #pragma unroll
            for (int j = 0; j < 4; j++) {
                wmma::fragment<wmma::matrix_b, 16, 16, 8, wmma::precision::tf32, wmma::col_major> bk;
                wmma::load_matrix_sync(bk, kc + j*16*AP + ks*8, AP);
                wmma::mma_sync(sacc[j], aq, bk, sacc[j]);
            }
        }
        #pragma unroll
        for (int j = 0; j < 4; j++)
            wmma::store_matrix_sync(Ps + rowm*AP + j*16, sacc[j], AP, wmma::mem_row_major);
        __syncwarp();

        // P = exp(S), tf32-rounded; accumulate row sums (no max needed).
        {
            const int rr = rowm + (lane >> 1);
            const int cc = (lane & 1) * 32;
            float* pr = Ps + rr*AP + cc;
            float sum = 0.f;
            #pragma unroll
            for (int j = 0; j < 32; j++) {
                float e = __expf(pr[j]);
                sum += e;
                pr[j] = to_tf32(e);
            }
            sum += __shfl_xor_sync(0xffffffffu, sum, 1);
            if (!(lane & 1)) lrow[rr] += sum;
        }
        __syncwarp();

        // O += P @ V
        #pragma unroll
        for (int ks = 0; ks < 8; ks++) {
            wmma::fragment<wmma::matrix_a, 16, 16, 8, wmma::precision::tf32, wmma::row_major> ap;
            wmma::load_matrix_sync(ap, Ps + rowm*AP + ks*8, AP);
            #pragma unroll
            for (int j = 0; j < 4; j++) {
                wmma::fragment<wmma::matrix_b, 16, 16, 8, wmma::precision::tf32, wmma::row_major> bv;
                wmma::load_matrix_sync(bv, vc + ks*8*AP + j*16, AP);
                wmma::mma_sync(oacc[j], ap, bv, oacc[j]);
            }
        }
        stg ^= 1;
        __syncthreads();
    }

    #pragma unroll
    for (int j = 0; j < 4; j++)
        wmma::store_matrix_sync(Ps + rowm*AP + j*16, oacc[j], AP, wmma::mem_row_major);
    __syncthreads();

    {
        const int r  = tid >> 1;
        const int c0 = (tid & 1) * 32;
        const float inv = 1.f / lrow[r];
        const float* srcr = Ps + r*AP + c0;
        float* dst = outp + (size_t)(b*Tn + q0 + r) * Dn + h*HDn + c0;
        #pragma unroll
        for (int j = 0; j < 8; j++) {
            float4 v;
            v.x = to_tf32(srcr[j*4+0] * inv);
            v.y = to_tf32(srcr[j*4+1] * inv);
            v.z = to_tf32(srcr[j*4+2] * inv);
            v.w = to_tf32(srcr[j*4+3] * inv);
            *(float4*)(dst + j*4) = v;
        }
    }
}

// ---------------------------------------------------------------------------
extern "C" void kernel_launch(void* const* d_in, const int* in_sizes, int n_in,
                              void* d_out, int out_size)
{
    const float* x    = (const float*)d_in[0];
    const float* Wqkv = (const float*)d_in[1];
    const float* Wo   = (const float*)d_in[2];
    const float* bo   = (const float*)d_in[3];
    float* out = (float*)d_out;

    float *qkv, *att, *xr, *wq, *wo;
    cudaGetSymbolAddress((void**)&qkv, g_qkv);
    cudaGetSymbolAddress((void**)&att, g_attn);
    cudaGetSymbolAddress((void**)&xr,  g_xr);
    cudaGetSymbolAddress((void**)&wq,  g_wq);
    cudaGetSymbolAddress((void**)&wo,  g_wo);

    cudaFuncSetAttribute(gemm_tf32_v3<0>,
                         cudaFuncAttributeMaxDynamicSharedMemorySize, GEMM_SMEM);
    cudaFuncSetAttribute(gemm_tf32_v3<1>,
                         cudaFuncAttributeMaxDynamicSharedMemorySize, GEMM_SMEM);
    cudaFuncSetAttribute(attn_tc_kernel,
                         cudaFuncAttributeMaxDynamicSharedMemorySize, ATT_SMEM);

    // 0) pre-round inputs to tf32
    {
        int n4;
        n4 = MROWS*Dn/4;   preround_kernel<<<(n4+255)/256, 256>>>(x,    xr, n4);
        n4 = Dn*QKVN/4;    preround_kernel<<<(n4+255)/256, 256>>>(Wqkv, wq, n4);
        n4 = Dn*Dn/4;      preround_kernel<<<(n4+255)/256, 256>>>(Wo,   wo, n4);
    }
    // 1) qkv = xr @ wq  (epilogue rounds to tf32)
    {
        dim3 grid(QKVN/128, MROWS/128);
        gemm_tf32_v3<1><<<grid, 256, GEMM_SMEM>>>(xr, wq, qkv, MROWS, QKVN, Dn);
    }
    // 2) RoPE + L2 norm (writes tf32)
    {
        int warps = Bn*Tn*Hn*2;
        rope_norm_kernel<<<warps/8, 256>>>(qkv);
    }
    // 3) attention (writes tf32)
    {
        dim3 grid(Bn * Hn * (Tn/128));
        attn_tc_kernel<<<grid, 256, ATT_SMEM>>>(qkv, att);
    }
    // 4) out = att @ wo + bo
    {
        dim3 grid(Dn/128, MROWS/128);
        gemm_tf32_v3<0><<<grid, 256, GEMM_SMEM>>>(att, wo, out, MROWS, Dn, Dn);
        int total4 = MROWS * Dn / 4;
        bias_add_kernel<<<(total4 + 255)/256, 256>>>(out, bo, total4, Dn);
    }
}

// round 6
// speedup vs baseline: 1.0687x; 1.0507x over previous
#include <cuda_runtime.h>
#include <mma.h>
#include <math.h>
#include <stdint.h>

using namespace nvcuda;

#define Bn 4
#define Tn 2048
#define Dn 1024
#define Hn 16
#define HDn 64
#define MROWS (Bn*Tn)      // 8192
#define QKVN (3*Dn)        // 3072

__device__ float g_qkv[(size_t)MROWS * QKVN];
__device__ float g_attn[(size_t)MROWS * Dn];
__device__ float g_xr[(size_t)MROWS * Dn];
__device__ float g_wq[(size_t)Dn * QKVN];
__device__ float g_wo[(size_t)Dn * Dn];

__device__ __forceinline__ float to_tf32(float x) {
    uint32_t u;
    asm("cvt.rna.tf32.f32 %0, %1;" : "=r"(u) : "f"(x));
    return __uint_as_float(u);
}
__device__ __forceinline__ uint32_t s2u(const void* p) {
    return (uint32_t)__cvta_generic_to_shared(p);
}
__device__ __forceinline__ void cp16(uint32_t dst, const void* src) {
    asm volatile("cp.async.cg.shared.global [%0], [%1], 16;" :: "r"(dst), "l"(src));
}
__device__ __forceinline__ void cp_commit() { asm volatile("cp.async.commit_group;"); }
__device__ __forceinline__ void cp_wait0()  { asm volatile("cp.async.wait_group 0;"); }

__global__ void __launch_bounds__(256) preround_kernel(
    const float* __restrict__ src, float* __restrict__ dst, int total4)
{
    int idx = blockIdx.x * blockDim.x + threadIdx.x;
    if (idx >= total4) return;
    float4 v = *(const float4*)&src[idx * 4];
    v.x = to_tf32(v.x); v.y = to_tf32(v.y);
    v.z = to_tf32(v.z); v.w = to_tf32(v.w);
    *(float4*)&dst[idx * 4] = v;
}

// ---------------------------------------------------------------------------
// TF32 GEMM: 128x128 tile, BK=32, cp.async double buffer. Inputs pre-rounded.
// __launch_bounds__(256,2): cap regs at 128 so 2 blocks/SM co-schedule.
// ---------------------------------------------------------------------------
#define AP_A 36
#define AP_B 132
#define A_STG (128*AP_A)
#define B_STG (32*AP_B)
#define GEMM_SMEM ((2*A_STG + 2*B_STG) * 4)

template <int ROUND_OUT>
__global__ void __launch_bounds__(256, 2) gemm_tf32_v3(
    const float* __restrict__ A, const float* __restrict__ Bm,
    float* __restrict__ C, int M, int N, int K)
{
    extern __shared__ float sm[];
    float* As = sm;
    float* Bs = sm + 2*A_STG;

    const int tid = threadIdx.x;
    const int bm = blockIdx.y * 128;
    const int bn = blockIdx.x * 128;
    const int w  = tid >> 5;
    const int wm = (w >> 2) * 64;
    const int wn = (w & 3) * 32;

    wmma::fragment<wmma::accumulator, 16, 16, 8, float> acc[4][2];
    #pragma unroll
    for (int i = 0; i < 4; i++)
        #pragma unroll
        for (int j = 0; j < 2; j++) wmma::fill_fragment(acc[i][j], 0.f);

    const int nk = K / 32;

    auto prefetch = [&](int kt, int stg) {
        const int k0 = kt * 32;
        float* ad = As + stg * A_STG;
        float* bd = Bs + stg * B_STG;
        #pragma unroll
        for (int i = 0; i < 4; i++) {
            int id = tid + 256*i;
            int r = id >> 3, c = (id & 7) * 4;
            cp16(s2u(ad + r*AP_A + c), &A[(size_t)(bm + r) * K + k0 + c]);
        }
        #pragma unroll
        for (int i = 0; i < 4; i++) {
            int id = tid + 256*i;
            int r = id >> 5, c = (id & 31) * 4;
            cp16(s2u(bd + r*AP_B + c), &Bm[(size_t)(k0 + r) * N + bn + c]);
        }
        cp_commit();
    };

    prefetch(0, 0);
    int stg = 0;

    for (int kt = 0; kt < nk; kt++) {
        cp_wait0();
        __syncthreads();
        if (kt + 1 < nk) prefetch(kt + 1, stg ^ 1);

        const float* a0 = As + stg * A_STG;
        const float* b0 = Bs + stg * B_STG;
        #pragma unroll
        for (int kk = 0; kk < 4; kk++) {
            wmma::fragment<wmma::matrix_a, 16, 16, 8, wmma::precision::tf32, wmma::row_major> af[4];
            wmma::fragment<wmma::matrix_b, 16, 16, 8, wmma::precision::tf32, wmma::row_major> bf[2];
            #pragma unroll
            for (int i = 0; i < 4; i++)
                wmma::load_matrix_sync(af[i], a0 + (wm + i*16)*AP_A + kk*8, AP_A);
            #pragma unroll
            for (int j = 0; j < 2; j++)
                wmma::load_matrix_sync(bf[j], b0 + (kk*8)*AP_B + wn + j*16, AP_B);
            #pragma unroll
            for (int i = 0; i < 4; i++)
                #pragma unroll
                for (int j = 0; j < 2; j++)
                    wmma::mma_sync(acc[i][j], af[i], bf[j], acc[i][j]);
        }
        stg ^= 1;
        __syncthreads();
    }

    #pragma unroll
    for (int i = 0; i < 4; i++)
        #pragma unroll
        for (int j = 0; j < 2; j++) {
            if (ROUND_OUT) {
                #pragma unroll
                for (int t = 0; t < acc[i][j].num_elements; t++)
                    acc[i][j].x[t] = to_tf32(acc[i][j].x[t]);
            }
            wmma::store_matrix_sync(&C[(size_t)(bm + wm + i*16) * N + bn + wn + j*16],
                                    acc[i][j], N, wmma::mem_row_major);
        }
}

__global__ void __launch_bounds__(256) bias_add_kernel(
    float* __restrict__ out, const float* __restrict__ bias, int total4, int N)
{
    int idx = blockIdx.x * blockDim.x + threadIdx.x;
    if (idx >= total4) return;
    int col = (idx * 4) & (N - 1);
    float4 v = *(float4*)&out[idx * 4];
    v.x += bias[col+0]; v.y += bias[col+1];
    v.z += bias[col+2]; v.w += bias[col+3];
    *(float4*)&out[idx * 4] = v;
}

// ---------------------------------------------------------------------------
// RoPE + L2 norm, writes tf32-rounded q,k in place.
// ---------------------------------------------------------------------------
__global__ void __launch_bounds__(256) rope_norm_kernel(float* __restrict__ qkv)
{
    const int gw = (blockIdx.x * blockDim.x + threadIdx.x) >> 5;
    const int lane = threadIdx.x & 31;
    const int which = gw & 1;
    const int h = (gw >> 1) & (Hn - 1);
    const int t = (gw >> 5) & (Tn - 1);
    const int b = gw >> 16;

    float* p = qkv + (size_t)(b*Tn + t) * QKVN + which*Dn + h*HDn;

    const float inv_freq = powf(10000.f, -(float)lane * (1.f/32.f));
    const float ang = (float)t * inv_freq;
    float s, c;
    sincosf(ang, &s, &c);

    const float x1 = p[lane];
    const float x2 = p[lane + 32];
    const float r1 = x1*c - x2*s;
    const float r2 = x1*s + x2*c;

    float ss = r1*r1 + r2*r2;
    #pragma unroll
    for (int off = 16; off; off >>= 1)
        ss += __shfl_xor_sync(0xffffffffu, ss, off);

    const float inv = rsqrtf(ss + 1e-6f);
    p[lane]      = to_tf32(r1 * inv);
    p[lane + 32] = to_tf32(r2 * inv);
}

// ---------------------------------------------------------------------------
// TF32 flash attention: 64 q-rows / 128 threads / 4 warps per block,
// cp.async double-buffered K/V. smem ~108KB -> 2 blocks/SM.
// q,k unit vectors -> |score|<=0.125 -> exp without max/rescale.
// ---------------------------------------------------------------------------
#define AP 72
#define KV_STG (64*AP)
#define ATT_SMEM ((64*AP + 2*KV_STG + 2*KV_STG + 64*AP + 64) * 4)

__global__ void __launch_bounds__(128) attn_tc_kernel(
    const float* __restrict__ qkv, float* __restrict__ outp)
{
    extern __shared__ float sm[];
    float* Qs   = sm;                        // 64 x AP (tf32)
    float* Ks   = Qs + 64*AP;                // 2 x 64 x AP
    float* Vs   = Ks + 2*KV_STG;             // 2 x 64 x AP
    float* Ps   = Vs + 2*KV_STG;             // 64 x AP
    float* lrow = Ps + 64*AP;                // 64

    const int tid  = threadIdx.x;
    const int w    = tid >> 5;               // 0..3
    const int lane = tid & 31;

    const int qt = blockIdx.x & 31;          // 32 q tiles of 64
    const int h  = (blockIdx.x >> 5) & (Hn-1);
    const int b  = blockIdx.x >> 9;
    const int q0 = qt * 64;

    const float* qbase = qkv + (size_t)(b*Tn) * QKVN + h*HDn;
    const float* kbase = qbase + Dn;
    const float* vbase = qbase + 2*Dn;

    auto prefetch_kv = [&](int kt, int stg) {
        float* kd = Ks + stg*KV_STG;
        float* vd = Vs + stg*KV_STG;
        #pragma unroll
        for (int i = 0; i < 8; i++) {
            int id = tid + 128*i;
            int r = id >> 4, c = (id & 15) * 4;
            cp16(s2u(kd + r*AP + c), kbase + (size_t)(kt*64 + r) * QKVN + c);
        }
        #pragma unroll
        for (int i = 0; i < 8; i++) {
            int id = tid + 128*i;
            int r = id >> 4, c = (id & 15) * 4;
            cp16(s2u(vd + r*AP + c), vbase + (size_t)(kt*64 + r) * QKVN + c);
        }
        cp_commit();
    };

    prefetch_kv(0, 0);

    // Q tile: scale by 1/8 (power of two => stays tf32)
    {
        const int r  = tid >> 1;             // 0..63
        const int c0 = (tid & 1) * 32;
        const float* src = qbase + (size_t)(q0 + r) * QKVN + c0;
        float* dst = Qs + r*AP + c0;
        #pragma unroll
        for (int j = 0; j < 8; j++) {
            float4 v = *(const float4*)(src + j*4);
            dst[j*4+0] = 0.125f * v.x;
            dst[j*4+1] = 0.125f * v.y;
            dst[j*4+2] = 0.125f * v.z;
            dst[j*4+3] = 0.125f * v.w;
        }
    }
    if (tid < 64) lrow[tid] = 0.f;

    wmma::fragment<wmma::accumulator, 16, 16, 8, float> oacc[4];
    #pragma unroll
    for (int j = 0; j < 4; j++) wmma::fill_fragment(oacc[j], 0.f);

    const int rowm = w * 16;
    int stg = 0;

    for (int kt = 0; kt < Tn/64; kt++) {
        cp_wait0();
        __syncthreads();
        if (kt + 1 < Tn/64) prefetch_kv(kt + 1, stg ^ 1);

        const float* kc = Ks + stg*KV_STG;
        const float* vc = Vs + stg*KV_STG;

        // S = Q @ K^T
        wmma::fragment<wmma::accumulator, 16, 16, 8, float> sacc[4];
        #pragma unroll
        for (int j = 0; j < 4; j++) wmma::fill_fragment(sacc[j], 0.f);
        #pragma unroll
        for (int ks = 0; ks < 8; ks++) {
            wmma::fragment<wmma::matrix_a, 16, 16, 8, wmma::precision::tf32, wmma::row_major> aq;
            wmma::load_matrix_sync(aq, Qs + rowm*AP + ks*8, AP);
            #pragma unroll
            for (int j = 0; j < 4; j++) {
                wmma::fragment<wmma::matrix_b, 16, 16, 8, wmma::precision::tf32, wmma::col_major> bk;
                wmma::load_matrix_sync(bk, kc + j*16*AP + ks*8, AP);
                wmma::mma_sync(sacc[j], aq, bk, sacc[j]);
            }
        }
        #pragma unroll
        for (int j = 0; j < 4; j++)
            wmma::store_matrix_sync(Ps + rowm*AP + j*16, sacc[j], AP, wmma::mem_row_major);
        __syncwarp();

        // P = exp(S), tf32-rounded; accumulate row sums (no max needed).
        {
            const int rr = rowm + (lane >> 1);
            const int cc = (lane & 1) * 32;
            float* pr = Ps + rr*AP + cc;
            float sum = 0.f;
            #pragma unroll
            for (int j = 0; j < 32; j++) {
                float e = __expf(pr[j]);
                sum += e;
                pr[j] = to_tf32(e);
            }
            sum += __shfl_xor_sync(0xffffffffu, sum, 1);
            if (!(lane & 1)) lrow[rr] += sum;
        }
        __syncwarp();

        // O += P @ V
        #pragma unroll
        for (int ks = 0; ks < 8; ks++) {
            wmma::fragment<wmma::matrix_a, 16, 16, 8, wmma::precision::tf32, wmma::row_major> ap;
            wmma::load_matrix_sync(ap, Ps + rowm*AP + ks*8, AP);
            #pragma unroll
            for (int j = 0; j < 4; j++) {
                wmma::fragment<wmma::matrix_b, 16, 16, 8, wmma::precision::tf32, wmma::row_major> bv;
                wmma::load_matrix_sync(bv, vc + ks*8*AP + j*16, AP);
                wmma::mma_sync(oacc[j], ap, bv, oacc[j]);
            }
        }
        stg ^= 1;
        __syncthreads();
    }

    #pragma unroll
    for (int j = 0; j < 4; j++)
        wmma::store_matrix_sync(Ps + rowm*AP + j*16, oacc[j], AP, wmma::mem_row_major);
    __syncthreads();

    {
        const int r  = tid >> 1;
        const int c0 = (tid & 1) * 32;
        const float inv = 1.f / lrow[r];
        const float* srcr = Ps + r*AP + c0;
        float* dst = outp + (size_t)(b*Tn + q0 + r) * Dn + h*HDn + c0;
        #pragma unroll
        for (int j = 0; j < 8; j++) {
            float4 v;
            v.x = to_tf32(srcr[j*4+0] * inv);
            v.y = to_tf32(srcr[j*4+1] * inv);
            v.z = to_tf32(srcr[j*4+2] * inv);
            v.w = to_tf32(srcr[j*4+3] * inv);
            *(float4*)(dst + j*4) = v;
        }
    }
}

// ---------------------------------------------------------------------------
extern "C" void kernel_launch(void* const* d_in, const int* in_sizes, int n_in,
                              void* d_out, int out_size)
{
    const float* x    = (const float*)d_in[0];
    const float* Wqkv = (const float*)d_in[1];
    const float* Wo   = (const float*)d_in[2];
    const float* bo   = (const float*)d_in[3];
    float* out = (float*)d_out;

    float *qkv, *att, *xr, *wq, *wo;
    cudaGetSymbolAddress((void**)&qkv, g_qkv);
    cudaGetSymbolAddress((void**)&att, g_attn);
    cudaGetSymbolAddress((void**)&xr,  g_xr);
    cudaGetSymbolAddress((void**)&wq,  g_wq);
    cudaGetSymbolAddress((void**)&wo,  g_wo);

    cudaFuncSetAttribute(gemm_tf32_v3<0>,
                         cudaFuncAttributeMaxDynamicSharedMemorySize, GEMM_SMEM);
    cudaFuncSetAttribute(gemm_tf32_v3<1>,
                         cudaFuncAttributeMaxDynamicSharedMemorySize, GEMM_SMEM);
    cudaFuncSetAttribute(attn_tc_kernel,
                         cudaFuncAttributeMaxDynamicSharedMemorySize, ATT_SMEM);

    // 0) pre-round inputs to tf32
    {
        int n4;
        n4 = MROWS*Dn/4;   preround_kernel<<<(n4+255)/256, 256>>>(x,    xr, n4);
        n4 = Dn*QKVN/4;    preround_kernel<<<(n4+255)/256, 256>>>(Wqkv, wq, n4);
        n4 = Dn*Dn/4;      preround_kernel<<<(n4+255)/256, 256>>>(Wo,   wo, n4);
    }
    // 1) qkv = xr @ wq  (epilogue rounds to tf32)
    {
        dim3 grid(QKVN/128, MROWS/128);
        gemm_tf32_v3<1><<<grid, 256, GEMM_SMEM>>>(xr, wq, qkv, MROWS, QKVN, Dn);
    }
    // 2) RoPE + L2 norm (writes tf32)
    {
        int warps = Bn*Tn*Hn*2;
        rope_norm_kernel<<<warps/8, 256>>>(qkv);
    }
    // 3) attention (writes tf32)
    {
        dim3 grid(Bn * Hn * (Tn/64));   // 2048
        attn_tc_kernel<<<grid, 128, ATT_SMEM>>>(qkv, att);
    }
    // 4) out = att @ wo + bo
    {
        dim3 grid(Dn/128, MROWS/128);
        gemm_tf32_v3<0><<<grid, 256, GEMM_SMEM>>>(att, wo, out, MROWS, Dn, Dn);
        int total4 = MROWS * Dn / 4;
        bias_add_kernel<<<(total4 + 255)/256, 256>>>(out, bo, total4, Dn);
    }
}